// round 9
// baseline (speedup 1.0000x reference)
#include <cuda_runtime.h>
#include <math.h>

#define DD 512
#define NN 128
#define TB 8

typedef unsigned long long ull;

__device__ float g_picked[NN];

// ---- packed f32x2 helpers (Blackwell FFMA2 path, PTX-only) -----------------
static __device__ __forceinline__ ull ffma2(ull a, ull b, ull c)
{
    ull d;
    asm("fma.rn.f32x2 %0, %1, %2, %3;" : "=l"(d) : "l"(a), "l"(b), "l"(c));
    return d;
}
static __device__ __forceinline__ ull pack2(float x, float y)
{
    ull d;
    asm("mov.b64 %0, {%1, %2};" : "=l"(d) : "f"(x), "f"(y));
    return d;
}
static __device__ __forceinline__ void unpack2(ull v, float& x, float& y)
{
    asm("mov.b64 {%0, %1}, %2;" : "=f"(x), "=f"(y) : "l"(v));
}

// ---------------------------------------------------------------------------
// One CTA (256 threads, 8 warps) per output row k.
// Omega (128x128) register-resident: warp w covers rows [16w,16w+16);
// lane l: row = 16w + (l>>1), half h = l&1 -> cols [64h, 64h+64) as 32
// packed f32x2 registers. The dot-product reduction is ONE shfl.xor(1).
// Per TB=8-site block:
//   phase1: w_b[row] = Omega[row]·p_b  (per-thread 64-dot + 1 shfl)  [b1]
//   gram:   S[a][b] = p_a·w_b  (warp a, shfl tree)                   [b2]
//   LU:     8x8 LU on S redundantly per warp; warp0 lane0 emits probs
//   fwdsub: y_j[row] in registers; publish Y_s                        [b3]
//   update: Omega[row][c] -= (y_j[row]·rd_j)·y_j[c]
// ---------------------------------------------------------------------------
__global__ void __launch_bounds__(256, 1)
sampler_kernel(const float* __restrict__ P, const int* __restrict__ pos,
               float* __restrict__ out)
{
    __shared__ __align__(16) float pv_s[2][TB][NN];
    __shared__ __align__(16) float wfin[TB][NN];
    __shared__ __align__(16) float Y_s[TB][NN];
    __shared__ __align__(16) float S_s[64];
    __shared__ unsigned char occ[DD];

    const int k    = blockIdx.x;
    const int tid  = threadIdx.x;
    const int lane = tid & 31;
    const int wid  = tid >> 5;              // 0..7
    const int row  = wid * 16 + (lane >> 1);
    const int h    = lane & 1;
    const int c0   = h * 64;

    for (int i = tid; i < DD; i += 256) occ[i] = 0;
    __syncthreads();
    if (tid < NN) occ[pos[tid]] = 1;

    const int myPos = pos[k];
    const int xmin  = (k == 0) ? 0 : (pos[k - 1] + 1);
    const int xmax  = DD - NN + k + 1;

    for (int i = tid; i < DD; i += 256) out[k * DD + i] = 0.0f;

    // Omega = I : A2[t] covers (row, cols c0+2t, c0+2t+1)
    ull A2[32];
#pragma unroll
    for (int t = 0; t < 32; t++)
        A2[t] = pack2((row == c0 + 2 * t) ? 1.0f : 0.0f,
                      (row == c0 + 2 * t + 1) ? 1.0f : 0.0f);

    // stage first block's 8 P rows: 1024 floats = 256 float4
    ((float4*)&pv_s[0][0][0])[tid] = __ldg((const float4*)P + tid);
    __syncthreads();

    float cprod = 1.0f;
    int buf = 0;
    for (int i0 = 0; i0 < xmax; i0 += TB) {
        const bool last = (i0 + TB >= xmax);

        float4 pf;
        if (!last) pf = __ldg((const float4*)(P + (i0 + TB) * NN) + tid);

        // ---- phase1: per b, 64-col partial dot + single shfl reduction
        float wreg[TB];
#pragma unroll
        for (int b = 0; b < TB; b++) {
            const ulonglong2* pb = (const ulonglong2*)&pv_s[buf][b][c0];
            ull a0 = 0ull, a1 = 0ull, a2 = 0ull, a3 = 0ull;
#pragma unroll
            for (int t = 0; t < 16; t += 2) {
                ulonglong2 u = pb[t];
                ulonglong2 v = pb[t + 1];
                a0 = ffma2(A2[2 * t],     u.x, a0);
                a1 = ffma2(A2[2 * t + 1], u.y, a1);
                a2 = ffma2(A2[2 * t + 2], v.x, a2);
                a3 = ffma2(A2[2 * t + 3], v.y, a3);
            }
            float x0, y0, x1, y1, x2, y2, x3, y3;
            unpack2(a0, x0, y0); unpack2(a1, x1, y1);
            unpack2(a2, x2, y2); unpack2(a3, x3, y3);
            float wb = ((x0 + y0) + (x1 + y1)) + ((x2 + y2) + (x3 + y3));
            wb += __shfl_xor_sync(0xffffffffu, wb, 1);   // add other half-row
            wreg[b] = wb;
            if (h == 0) wfin[b][row] = wb;
        }
        if (!last) ((float4*)&pv_s[buf ^ 1][0][0])[tid] = pf;
        __syncthreads();                               // --- b1 ---

        // ---- Gram: warp 'wid' computes S[wid][b] = sum_r p_wid[r]*w_b[r]
        {
            float4 pa = ((const float4*)&pv_s[buf][wid][0])[lane];
            float sg[TB];
#pragma unroll
            for (int b = 0; b < TB; b++) {
                float4 wb4 = ((const float4*)&wfin[b][0])[lane];
                sg[b] = pa.x * wb4.x + pa.y * wb4.y + pa.z * wb4.z + pa.w * wb4.w;
            }
#pragma unroll
            for (int off = 16; off; off >>= 1) {
#pragma unroll
                for (int b = 0; b < TB; b++)
                    sg[b] += __shfl_xor_sync(0xffffffffu, sg[b], off);
            }
            if (lane == 0) {
                *(float4*)&S_s[wid * 8]     = make_float4(sg[0], sg[1], sg[2], sg[3]);
                *(float4*)&S_s[wid * 8 + 4] = make_float4(sg[4], sg[5], sg[6], sg[7]);
            }
        }
        __syncthreads();                               // --- b2 ---

        // ---- redundant warp-local 8x8 LU on S; lane a<8 holds row a of S
        const int Teff = last ? (xmax - i0) : TB;
        float S_row[TB];
        if (lane < TB) {
            float4 s0 = *(const float4*)&S_s[lane * 8];
            float4 s1 = *(const float4*)&S_s[lane * 8 + 4];
            S_row[0] = s0.x; S_row[1] = s0.y; S_row[2] = s0.z; S_row[3] = s0.w;
            S_row[4] = s1.x; S_row[5] = s1.y; S_row[6] = s1.z; S_row[7] = s1.w;
        } else {
#pragma unroll
            for (int b = 0; b < TB; b++) S_row[b] = 0.0f;
        }
        float Lcol[TB];
        float rdv[TB];
        float cp = cprod;
#pragma unroll
        for (int j = 0; j < TB; j++) {
            if (j >= Teff) break;
            float rj[TB];
#pragma unroll
            for (int b = 0; b < TB; b++)
                rj[b] = __shfl_sync(0xffffffffu, S_row[b], j);
            const float beta = rj[j];
            const int i = i0 + j;
            const bool inwin = (i >= xmin);
            if (wid == 0 && lane == 0 && inwin) {
                float prob = cp * beta;
                float pcl = (fabsf(prob) > 1e-15f) ? prob : 0.0f;
                out[k * DD + i] = pcl;
                if (i == myPos) g_picked[k] = pcl;
            }
            if (inwin) cp *= (1.0f - beta);
            if (i == xmax - 1) break;      // forced last site: no elimination
            const float d  = (!inwin && occ[i]) ? beta : (beta - 1.0f);
            const float rd = 1.0f / d;
            rdv[j] = rd;
            const float mult = S_row[j] * rd;   // = L[lane][j]
            Lcol[j] = mult;
#pragma unroll
            for (int b = 0; b < TB; b++)
                S_row[b] = fmaf(-mult, rj[b], S_row[b]);
        }
        cprod = cp;
        if (last) break;

        // ---- forward substitution in registers (y aliases wreg):
        //      y_j = w_j - sum_{m<j} L[j][m] y_m
#pragma unroll
        for (int j = 1; j < TB; j++) {
#pragma unroll
            for (int m = 0; m < j; m++) {
                float ljm = __shfl_sync(0xffffffffu, Lcol[m], j);
                wreg[j] = fmaf(-ljm, wreg[m], wreg[j]);
            }
        }
        if (h == 0) {
#pragma unroll
            for (int j = 0; j < TB; j++) Y_s[j][row] = wreg[j];
        }
        __syncthreads();                               // --- b3 ---

        // ---- rank-8 update: Omega[row][c] -= (y_j[row]*rd_j) * y_j[c]
#pragma unroll
        for (int j = 0; j < TB; j++) {
            float nz = -(wreg[j] * rdv[j]);
            ull nz2 = pack2(nz, nz);
            const ulonglong2* yb = (const ulonglong2*)&Y_s[j][c0];
#pragma unroll
            for (int t = 0; t < 16; t += 2) {
                ulonglong2 u = yb[t];
                ulonglong2 v = yb[t + 1];
                A2[2 * t]     = ffma2(nz2, u.x, A2[2 * t]);
                A2[2 * t + 1] = ffma2(nz2, u.y, A2[2 * t + 1]);
                A2[2 * t + 2] = ffma2(nz2, v.x, A2[2 * t + 2]);
                A2[2 * t + 3] = ffma2(nz2, v.y, A2[2 * t + 3]);
            }
        }
        buf ^= 1;
    }
}

// ---------------------------------------------------------------------------
// Parallel log-sum of picked probabilities (one warp, tree reduction).
// ---------------------------------------------------------------------------
__global__ void logsum_kernel(float* __restrict__ out_scalar)
{
    int lane = threadIdx.x;
    float s = 0.0f;
    for (int k = lane; k < NN; k += 32) s += logf(g_picked[k]);
#pragma unroll
    for (int o = 16; o; o >>= 1) s += __shfl_xor_sync(0xffffffffu, s, o);
    if (lane == 0) *out_scalar = s;
}

extern "C" void kernel_launch(void* const* d_in, const int* in_sizes, int n_in,
                              void* d_out, int out_size)
{
    const float* P = (const float*)d_in[0];    // [D, N] float32
    const int* pos = (const int*)d_in[1];      // [N] int32, sorted
    float* out = (float*)d_out;                // [N*D probs][1 logprob]

    sampler_kernel<<<NN, 256>>>(P, pos, out);
    logsum_kernel<<<1, 32>>>(out + (out_size - 1));
}